// round 6
// baseline (speedup 1.0000x reference)
#include <cuda_runtime.h>
#include <math.h>

#define B_DIM 64
#define T_DIM 1000
#define P_ORD 10
#define NFRAMES (B_DIM * T_DIM)
#define PI_D 3.14159265358979323846
#define FULLMASK 0xffffffffu

__device__ double d_M[121];
__device__ float d_x0[20];
__device__ float g_pc[NFRAMES * 12];   // 11 coeffs per frame, stride 12

// Parallel init: one block per matrix entry (j,d); threads split the k-sum.
__global__ void init_consts_kernel() {
    __shared__ double red[128];
    int e = blockIdx.x;
    int j = e / 11, d = e % 11;
    int k = threadIdx.x;

    double term = 0.0;
    if (k >= 1 && k <= 114) {
        double gd = (d == 0) ? 1.0 : 2.0 * cos(2.0 * PI_D * (double)k * (double)d / 512.0);
        term = 2.0 * gd * cos(2.0 * PI_D * (double)k * (double)j / 230.0);
    }
    red[threadIdx.x] = term;
    __syncthreads();
#pragma unroll
    for (int s = 64; s > 0; s >>= 1) {
        if (threadIdx.x < s) red[threadIdx.x] += red[threadIdx.x + s];
        __syncthreads();
    }
    if (threadIdx.x == 0) {
        double s = red[0];
        s += (d == 0) ? 1.0 : 2.0;                               // k = 0 bin
        double g115 = (d == 0) ? 1.0 : 2.0 * cos(2.0 * PI_D * 115.0 * (double)d / 512.0);
        s += ((j & 1) ? -1.0 : 1.0) * g115;                      // k = 115 Nyquist
        d_M[e] = s / 230.0;
    }
    if (e == 0 && threadIdx.x == 127) {
        double cr = 1.0, ci = 0.0;
        for (int p = 0; p < 10; p++) {
            double nr = cr * 0.4 - ci * 0.9;
            double ni = cr * 0.9 + ci * 0.4;
            cr = nr; ci = ni;
            d_x0[p]      = (float)nr;
            d_x0[10 + p] = (float)ni;
        }
    }
}

// ===== Front-end: fp64, one thread per frame, writes pc[0..10] to scratch =====
__global__ void frontend_kernel(const float* __restrict__ in) {
    __shared__ double sM[121];
    if (threadIdx.x < 121) sM[threadIdx.x] = d_M[threadIdx.x];
    __syncthreads();

    int frame = blockIdx.x * 128 + threadIdx.x;
    if (frame >= NFRAMES) return;
    int b = frame / T_DIM;
    int t = frame - b * T_DIM;
    const float* base = in + (size_t)b * (P_ORD * T_DIM) + t;

    double A[11];
    A[0] = 1.0;
    {
        double a[10];
        a[0] = (double)base[0];
#pragma unroll
        for (int p = 1; p < 10; p++) {
            double k = (double)base[p * T_DIM];
            double na[10];
#pragma unroll
            for (int i = 0; i < p; i++) na[i] = a[i] + k * a[p - 1 - i];
#pragma unroll
            for (int i = 0; i < p; i++) a[i] = na[i];
            a[p] = k;
        }
#pragma unroll
        for (int i = 0; i < 10; i++) A[i + 1] = a[i];
    }

    double c[11];
#pragma unroll
    for (int d = 0; d < 11; d++) {
        double s = 0.0;
#pragma unroll
        for (int n = 0; n < 11 - d; n++) s = fma(A[n], A[n + d], s);
        c[d] = s;
    }

    double r[11];
#pragma unroll
    for (int j = 0; j < 11; j++) {
        double s = 0.0;
#pragma unroll
        for (int d = 0; d < 11; d++) s = fma(sM[j * 11 + d], c[d], s);
        r[j] = s;
    }

    float* pcd = &g_pc[(size_t)frame * 12];
    pcd[0] = 1.0f;
    {
        double a[10];
        double k0 = -r[1] / r[0];
        a[0] = k0;
        double err = r[0] * (1.0 - k0 * k0);
#pragma unroll
        for (int m = 1; m < 10; m++) {
            double acc = r[m + 1];
#pragma unroll
            for (int i = 0; i < m; i++) acc = fma(a[i], r[m - i], acc);
            double k = -acc / err;
            double na[10];
#pragma unroll
            for (int i = 0; i < m; i++) na[i] = a[i] + k * a[m - 1 - i];
#pragma unroll
            for (int i = 0; i < m; i++) a[i] = na[i];
            a[m] = k;
            err *= (1.0 - k * k);
        }
#pragma unroll
        for (int i = 0; i < 10; i++) pcd[i + 1] = (float)a[i];
    }
}

// XLA-faithful complex division: Smith + __divsc3-style recovery, IEEE rn.
__device__ __forceinline__ void cdivf(float a, float b, float c, float d,
                                      float& outr, float& outi) {
    float re, im;
    if (fabsf(c) >= fabsf(d)) {
        float r     = __fdiv_rn(d, c);
        float denom = __fadd_rn(c, __fmul_rn(d, r));
        re = __fdiv_rn(__fadd_rn(a, __fmul_rn(b, r)), denom);
        im = __fdiv_rn(__fsub_rn(b, __fmul_rn(a, r)), denom);
    } else {
        float r     = __fdiv_rn(c, d);
        float denom = __fadd_rn(__fmul_rn(c, r), d);
        re = __fdiv_rn(__fadd_rn(__fmul_rn(a, r), b), denom);
        im = __fdiv_rn(__fsub_rn(__fmul_rn(b, r), a), denom);
    }
    if (isnan(re) && isnan(im)) {
        if ((c == 0.0f && d == 0.0f) && (!isnan(a) || !isnan(b))) {
            re = copysignf(INFINITY, c) * a;
            im = copysignf(INFINITY, c) * b;
        } else if ((isinf(a) || isinf(b)) && isfinite(c) && isfinite(d)) {
            float aa = copysignf(isinf(a) ? 1.0f : 0.0f, a);
            float bb = copysignf(isinf(b) ? 1.0f : 0.0f, b);
            re = INFINITY * __fadd_rn(__fmul_rn(aa, c), __fmul_rn(bb, d));
            im = INFINITY * __fsub_rn(__fmul_rn(bb, c), __fmul_rn(aa, d));
        } else if ((isinf(c) || isinf(d)) && isfinite(a) && isfinite(b)) {
            float cc = copysignf(isinf(c) ? 1.0f : 0.0f, c);
            float dd = copysignf(isinf(d) ? 1.0f : 0.0f, d);
            re = 0.0f * __fadd_rn(__fmul_rn(a, cc), __fmul_rn(b, dd));
            im = 0.0f * __fsub_rn(__fmul_rn(b, cc), __fmul_rn(a, dd));
        }
    }
    outr = re; outi = im;
}

// ===== Durand-Kerner: 2 threads per frame, 5 roots each, fp32 =====
__global__ void __launch_bounds__(256)
dk_kernel(float* __restrict__ out) {
    int gtid  = blockIdx.x * 256 + threadIdx.x;
    int frame = gtid >> 1;
    int half  = gtid & 1;

    // predictor polynomial
    float pc[11];
    const float* pcd = &g_pc[(size_t)frame * 12];
#pragma unroll
    for (int i = 0; i < 11; i++) pc[i] = pcd[i];

    float x[5], y[5];
#pragma unroll
    for (int i = 0; i < 5; i++) {
        x[i] = d_x0[half * 5 + i];
        y[i] = d_x0[10 + half * 5 + i];
    }

#pragma unroll 1
    for (int it = 0; it < 30; it++) {
        // gather all 10 roots in global order (width-2 shuffles)
        float R[10], Ii[10];
#pragma unroll
        for (int g = 0; g < 10; g++) {
            R[g]  = __shfl_sync(FULLMASK, x[g % 5], g / 5, 2);
            Ii[g] = __shfl_sync(FULLMASK, y[g % 5], g / 5, 2);
        }

        float nx[5], ny[5];
#pragma unroll
        for (int i = 0; i < 5; i++) {
            float X = x[i], Y = y[i];
            // Horner polyval (sequential, unfused — verbatim R5 ops)
            float yr = pc[0], yi = 0.f;
#pragma unroll
            for (int m = 1; m <= 10; m++) {
                float tr = __fadd_rn(__fsub_rn(__fmul_rn(yr, X), __fmul_rn(yi, Y)), pc[m]);
                float ti = __fadd_rn(__fmul_rn(yr, Y), __fmul_rn(yi, X));
                yr = tr; yi = ti;
            }
            // product over j = 0..9 global order; eye only possible at j%5 == i
            float dr, di;
            {   // j = 0 factor folded: (1,0)*(er,ei) == (er,ei) bit-exactly
                float eye = (0 % 5 == i) ? ((half == 0 && i == 0) ? 1.f : 0.f) : 0.f;
                float er = __fsub_rn(X, R[0]);
                if (0 % 5 == i) er = __fadd_rn(er, eye);
                dr = er;
                di = __fsub_rn(Y, Ii[0]);
            }
#pragma unroll
            for (int j = 1; j < 10; j++) {
                float er = __fsub_rn(X, R[j]);
                if (j % 5 == i) {
                    float eye = (half == (j >= 5 ? 1 : 0)) ? 1.f : 0.f;
                    er = __fadd_rn(er, eye);
                }
                float ei = __fsub_rn(Y, Ii[j]);
                float tr = __fsub_rn(__fmul_rn(dr, er), __fmul_rn(di, ei));
                float ti = __fadd_rn(__fmul_rn(dr, ei), __fmul_rn(di, er));
                dr = tr; di = ti;
            }
            dr = __fadd_rn(dr, 1e-12f);
            float qr, qi;
            cdivf(yr, yi, dr, di, qr, qi);
            nx[i] = __fsub_rn(X, qr);
            ny[i] = __fsub_rn(Y, qi);
        }
#pragma unroll
        for (int i = 0; i < 5; i++) { x[i] = nx[i]; y[i] = ny[i]; }
    }

    // ---- roots -> formants, exchange, sort, write (even lane) ----
    float f5[5];
#pragma unroll
    for (int i = 0; i < 5; i++) {
        float fr = atan2f(y[i], x[i]) * (10000.0f / (2.0f * (float)PI_D));
        bool valid = (y[i] > 0.f) && (fr > 50.0f) && (fr < 4950.0f);
        f5[i] = valid ? fr : 10000.0f;
    }
    float pf[5];
#pragma unroll
    for (int j = 0; j < 5; j++) pf[j] = __shfl_xor_sync(FULLMASK, f5[j], 1);

    float f[10];
#pragma unroll
    for (int j = 0; j < 5; j++) {
        f[j]     = half ? pf[j] : f5[j];
        f[5 + j] = half ? f5[j] : pf[j];
    }
#pragma unroll
    for (int pass = 0; pass < 9; pass++) {
#pragma unroll
        for (int i = 0; i < 9; i++) {
            float lo = fminf(f[i], f[i + 1]);
            float hi = fmaxf(f[i], f[i + 1]);
            f[i] = lo; f[i + 1] = hi;
        }
    }

    if (half == 0) {
        int b = frame / T_DIM;
        int t = frame - b * T_DIM;
        float* ob = out + (size_t)b * (4 * T_DIM) + t;
#pragma unroll
        for (int q = 0; q < 4; q++)
            ob[q * T_DIM] = 2.0f * f[q] / 11025.0f - 1.0f;
    }
}

extern "C" void kernel_launch(void* const* d_in, const int* in_sizes, int n_in,
                              void* d_out, int out_size) {
    const float* in = (const float*)d_in[0];
    float* out = (float*)d_out;
    (void)in_sizes; (void)n_in; (void)out_size;

    init_consts_kernel<<<121, 128>>>();
    frontend_kernel<<<(NFRAMES + 127) / 128, 128>>>(in);
    dk_kernel<<<(NFRAMES * 2) / 256, 256>>>(out);
}